// round 4
// baseline (speedup 1.0000x reference)
#include <cuda_runtime.h>

// Problem constants
#define NHEADS 16
#define DHEAD  64
#define NTILE  64
#define TILE   128
#define SEQ    8192
#define HID    1024

// Scratch: tiled Q/K/V/O, layout [NH][NTILE][TILE][D], values tf32-rounded
__device__ float g_q[NHEADS * NTILE * TILE * DHEAD];
__device__ float g_k[NHEADS * NTILE * TILE * DHEAD];
__device__ float g_v[NHEADS * NTILE * TILE * DHEAD];
__device__ float g_o[NHEADS * NTILE * TILE * DHEAD];

__device__ __forceinline__ void seq_to_tile(int s, int& n, int& p) {
    int t = s >> 10;
    int h = (s >> 5) & 31;
    int w = s & 31;
    n = (((t >> 1) * 4 + (h >> 3)) * 4 + (w >> 3));
    p = (((t & 1) * 8 + (h & 7)) * 8 + (w & 7));
}

__device__ __forceinline__ unsigned f2tf32(float x) {
    unsigned u;
    asm("cvt.rna.tf32.f32 %0, %1;" : "=r"(u) : "f"(x));
    return u;
}
__device__ __forceinline__ float tff(float x) { return __uint_as_float(f2tf32(x)); }

__device__ __forceinline__ float ex2(float x) {
    float y;
    asm("ex2.approx.f32 %0, %1;" : "=f"(y) : "f"(x));
    return y;
}

__device__ __forceinline__ void mma_tf32(float& c0, float& c1, float& c2, float& c3,
                                         unsigned a0, unsigned a1, unsigned a2, unsigned a3,
                                         unsigned b0, unsigned b1) {
    asm volatile(
        "mma.sync.aligned.m16n8k8.row.col.f32.tf32.tf32.f32 "
        "{%0,%1,%2,%3},{%4,%5,%6,%7},{%8,%9},{%0,%1,%2,%3};"
        : "+f"(c0), "+f"(c1), "+f"(c2), "+f"(c3)
        : "r"(a0), "r"(a1), "r"(a2), "r"(a3), "r"(b0), "r"(b1));
}

// ---------------------------------------------------------------------------
// QKV projection: 128x128 block tile, 4 warps (2x2), warp tile 64x64, K-chunk 32.
// grid (8, 64, 3). Epilogue writes tf32-rounded values into tiled layout.
// ---------------------------------------------------------------------------
__global__ __launch_bounds__(128) void qkv_gemm(
    const float* __restrict__ X,
    const float* __restrict__ Wq,
    const float* __restrict__ Wk,
    const float* __restrict__ Wv)
{
    const float* W = (blockIdx.z == 0) ? Wq : (blockIdx.z == 1) ? Wk : Wv;
    float* Out = (blockIdx.z == 0) ? g_q : (blockIdx.z == 1) ? g_k : g_v;

    const int m0 = blockIdx.y * 128;
    const int n0 = blockIdx.x * 128;

    __shared__ float As[128 * 36];   // [m][k] stride 36
    __shared__ float Bs[32 * 136];   // [k][n] stride 136

    const int tid = threadIdx.x;
    const int warp = tid >> 5, lane = tid & 31;
    const int g = lane >> 2, c = lane & 3;
    const int wm = warp >> 1, wn = warp & 1;

    float acc[4][8][4] = {};

    for (int kk = 0; kk < HID; kk += 32) {
        #pragma unroll
        for (int l = 0; l < 8; l++) {
            int e = tid + l * 128;
            int row = e >> 3, c4 = e & 7;
            float4 v = *(const float4*)&X[(m0 + row) * HID + kk + c4 * 4];
            v.x = tff(v.x); v.y = tff(v.y); v.z = tff(v.z); v.w = tff(v.w);
            *(float4*)&As[row * 36 + c4 * 4] = v;
        }
        #pragma unroll
        for (int l = 0; l < 8; l++) {
            int e = tid + l * 128;
            int k = e >> 5, c4 = e & 31;
            float4 v = *(const float4*)&W[(kk + k) * HID + n0 + c4 * 4];
            v.x = tff(v.x); v.y = tff(v.y); v.z = tff(v.z); v.w = tff(v.w);
            *(float4*)&Bs[k * 136 + c4 * 4] = v;
        }
        __syncthreads();

        #pragma unroll
        for (int ks = 0; ks < 4; ks++) {
            unsigned a[4][4], b[8][2];
            #pragma unroll
            for (int mf = 0; mf < 4; mf++) {
                const float* p = &As[(wm * 64 + mf * 16 + g) * 36 + ks * 8 + c];
                a[mf][0] = __float_as_uint(p[0]);
                a[mf][1] = __float_as_uint(p[8 * 36]);
                a[mf][2] = __float_as_uint(p[4]);
                a[mf][3] = __float_as_uint(p[8 * 36 + 4]);
            }
            #pragma unroll
            for (int nf = 0; nf < 8; nf++) {
                int col = wn * 64 + nf * 8 + g;
                b[nf][0] = __float_as_uint(Bs[(ks * 8 + c) * 136 + col]);
                b[nf][1] = __float_as_uint(Bs[(ks * 8 + c + 4) * 136 + col]);
            }
            #pragma unroll
            for (int mf = 0; mf < 4; mf++)
                #pragma unroll
                for (int nf = 0; nf < 8; nf++)
                    mma_tf32(acc[mf][nf][0], acc[mf][nf][1], acc[mf][nf][2], acc[mf][nf][3],
                             a[mf][0], a[mf][1], a[mf][2], a[mf][3], b[nf][0], b[nf][1]);
        }
        __syncthreads();
    }

    #pragma unroll
    for (int mf = 0; mf < 4; mf++) {
        int r0 = m0 + wm * 64 + mf * 16 + g;
        int r1 = r0 + 8;
        int n_, p_, n2, p2;
        seq_to_tile(r0, n_, p_);
        seq_to_tile(r1, n2, p2);
        #pragma unroll
        for (int nf = 0; nf < 8; nf++) {
            int colg = n0 + wn * 64 + nf * 8 + 2 * c;
            int head = colg >> 6, d = colg & 63;
            float2 v0 = make_float2(tff(acc[mf][nf][0]), tff(acc[mf][nf][1]));
            float2 v1 = make_float2(tff(acc[mf][nf][2]), tff(acc[mf][nf][3]));
            *(float2*)&Out[((head * NTILE + n_) * TILE + p_) * DHEAD + d] = v0;
            *(float2*)&Out[((head * NTILE + n2) * TILE + p2) * DHEAD + d] = v1;
        }
    }
}

// ---------------------------------------------------------------------------
// Flash attention. 1 block per (head, q-tile): 1024 blocks, 8 warps, warp owns
// 16 q rows. 64-key chunks. P never touches smem: the S C-fragment is reused
// directly as the PV A-fragment under the column permutation sigma(c)=2c,
// sigma(c+4)=2c+1, compensated by reading V B-frag rows 2c and 2c+1.
// ---------------------------------------------------------------------------
__global__ __launch_bounds__(256) void attn_kernel()
{
    const int bid = blockIdx.x;
    const int head = bid >> 6;
    const int n = bid & 63;
    const int tid = threadIdx.x;
    const int warp = tid >> 5, lane = tid & 31;
    const int g = lane >> 2, c = lane & 3;

    __shared__ float Ks[64 * 68];   // [key][d] stride 68
    __shared__ float Vs[64 * 68];

    const float SC = 0.125f * 1.4426950408889634f;   // 1/sqrt(D) * log2e
    unsigned Qf[8][4];
    {
        const float* qb = &g_q[(size_t)((head * NTILE + n) * TILE) * DHEAD];
        int r = warp * 16 + g;
        #pragma unroll
        for (int kf = 0; kf < 8; kf++) {
            int col = kf * 8 + c;
            Qf[kf][0] = f2tf32(qb[r * 64 + col] * SC);
            Qf[kf][1] = f2tf32(qb[(r + 8) * 64 + col] * SC);
            Qf[kf][2] = f2tf32(qb[r * 64 + col + 4] * SC);
            Qf[kf][3] = f2tf32(qb[(r + 8) * 64 + col + 4] * SC);
        }
    }

    float O[8][4] = {};
    float m0 = -1e30f, m1 = -1e30f, l0 = 0.f, l1 = 0.f;

    const int ntt = n >> 4, nth = (n >> 2) & 3, ntw = n & 3;
    const int ct = min(max(ntt, 1), 2);
    const int ch = min(max(nth, 1), 3);
    const int cw = min(max(ntw, 1), 3);

    for (int kk = 0; kk < 12; kk++) {
        const int it = kk >> 2, ih = (kk >> 1) & 1, iw = kk & 1;
        const int kvn = ((ct - 1 + it) * 4 + (ch - 1 + ih)) * 4 + (cw - 1 + iw);
        const float* kb = &g_k[(size_t)((head * NTILE + kvn) * TILE) * DHEAD];
        const float* vb = &g_v[(size_t)((head * NTILE + kvn) * TILE) * DHEAD];

        for (int cc = 0; cc < 2; cc++) {
            __syncthreads();
            #pragma unroll
            for (int l2 = 0; l2 < 4; l2++) {
                int e = tid + l2 * 256;
                int key = e >> 4, c4 = e & 15;
                *(float4*)&Ks[key * 68 + c4 * 4] =
                    *(const float4*)&kb[(cc * 64 + key) * 64 + c4 * 4];
                *(float4*)&Vs[key * 68 + c4 * 4] =
                    *(const float4*)&vb[(cc * 64 + key) * 64 + c4 * 4];
            }
            __syncthreads();

            // S = Q*K^T (pre-scaled): 16 rows x 64 keys per warp
            float S[8][4] = {};
            #pragma unroll
            for (int ks = 0; ks < 8; ks++) {
                #pragma unroll
                for (int nf = 0; nf < 8; nf++) {
                    int key = nf * 8 + g;
                    unsigned b0 = __float_as_uint(Ks[key * 68 + ks * 8 + c]);
                    unsigned b1 = __float_as_uint(Ks[key * 68 + ks * 8 + c + 4]);
                    mma_tf32(S[nf][0], S[nf][1], S[nf][2], S[nf][3],
                             Qf[ks][0], Qf[ks][1], Qf[ks][2], Qf[ks][3], b0, b1);
                }
            }

            // online softmax (base-2): rows r=16w+g and r+8; 4 lanes per row
            float rmax0 = -1e30f, rmax1 = -1e30f;
            #pragma unroll
            for (int nf = 0; nf < 8; nf++) {
                rmax0 = fmaxf(rmax0, fmaxf(S[nf][0], S[nf][1]));
                rmax1 = fmaxf(rmax1, fmaxf(S[nf][2], S[nf][3]));
            }
            rmax0 = fmaxf(rmax0, __shfl_xor_sync(0xffffffffu, rmax0, 1));
            rmax0 = fmaxf(rmax0, __shfl_xor_sync(0xffffffffu, rmax0, 2));
            rmax1 = fmaxf(rmax1, __shfl_xor_sync(0xffffffffu, rmax1, 1));
            rmax1 = fmaxf(rmax1, __shfl_xor_sync(0xffffffffu, rmax1, 2));

            float mn0 = fmaxf(m0, rmax0), mn1 = fmaxf(m1, rmax1);
            float sf0 = ex2(m0 - mn0), sf1 = ex2(m1 - mn1);

            float rs0 = 0.f, rs1 = 0.f;
            #pragma unroll
            for (int nf = 0; nf < 8; nf++) {
                S[nf][0] = ex2(S[nf][0] - mn0);
                S[nf][1] = ex2(S[nf][1] - mn0);
                S[nf][2] = ex2(S[nf][2] - mn1);
                S[nf][3] = ex2(S[nf][3] - mn1);
                rs0 += S[nf][0] + S[nf][1];
                rs1 += S[nf][2] + S[nf][3];
            }
            rs0 += __shfl_xor_sync(0xffffffffu, rs0, 1);
            rs0 += __shfl_xor_sync(0xffffffffu, rs0, 2);
            rs1 += __shfl_xor_sync(0xffffffffu, rs1, 1);
            rs1 += __shfl_xor_sync(0xffffffffu, rs1, 2);

            l0 = l0 * sf0 + rs0;
            l1 = l1 * sf1 + rs1;
            m0 = mn0; m1 = mn1;

            #pragma unroll
            for (int nf = 0; nf < 8; nf++) {
                O[nf][0] *= sf0; O[nf][1] *= sf0;
                O[nf][2] *= sf1; O[nf][3] *= sf1;
            }

            // O += P*V, P fed straight from the S fragment (permuted A):
            // (a0,a1,a2,a3) = (c0,c2,c1,c3); V rows read at 2c and 2c+1.
            #pragma unroll
            for (int ko = 0; ko < 8; ko++) {
                unsigned pa0 = f2tf32(S[ko][0]);
                unsigned pa1 = f2tf32(S[ko][2]);
                unsigned pa2 = f2tf32(S[ko][1]);
                unsigned pa3 = f2tf32(S[ko][3]);
                #pragma unroll
                for (int nf = 0; nf < 8; nf++) {
                    unsigned vb0 = __float_as_uint(Vs[(ko * 8 + 2 * c) * 68 + nf * 8 + g]);
                    unsigned vb1 = __float_as_uint(Vs[(ko * 8 + 2 * c + 1) * 68 + nf * 8 + g]);
                    mma_tf32(O[nf][0], O[nf][1], O[nf][2], O[nf][3],
                             pa0, pa1, pa2, pa3, vb0, vb1);
                }
            }
        }
    }

    const float inv0 = 1.f / l0, inv1 = 1.f / l1;
    float* ob = &g_o[(size_t)((head * NTILE + n) * TILE) * DHEAD];
    int r = warp * 16 + g;
    #pragma unroll
    for (int nf = 0; nf < 8; nf++) {
        int col = nf * 8 + 2 * c;
        *(float2*)&ob[r * 64 + col] =
            make_float2(tff(O[nf][0] * inv0), tff(O[nf][1] * inv0));
        *(float2*)&ob[(r + 8) * 64 + col] =
            make_float2(tff(O[nf][2] * inv1), tff(O[nf][3] * inv1));
    }
}

// ---------------------------------------------------------------------------
// Output projection: out = O_seq @ Wo, _from_tiles remap fused into A fill.
// 128x128 block tile, 4 warps. grid (8, 64).
// ---------------------------------------------------------------------------
__global__ __launch_bounds__(128) void oproj_gemm(
    const float* __restrict__ Wo, float* __restrict__ out)
{
    const int m0 = blockIdx.y * 128;
    const int n0 = blockIdx.x * 128;

    __shared__ float As[128 * 36];
    __shared__ float Bs[32 * 136];

    const int tid = threadIdx.x;
    const int warp = tid >> 5, lane = tid & 31;
    const int g = lane >> 2, c = lane & 3;
    const int wm = warp >> 1, wn = warp & 1;

    // hoist the tile remap for this thread's 8 A rows
    int rowoff[8];
    #pragma unroll
    for (int l = 0; l < 8; l++) {
        int e = tid + l * 128;
        int row = e >> 3;
        int nn, pp;
        seq_to_tile(m0 + row, nn, pp);
        rowoff[l] = nn * TILE + pp;
    }

    float acc[4][8][4] = {};

    for (int kk = 0; kk < HID; kk += 32) {
        const int hk = kk >> 6;
        const int dbase = kk & 63;
        const float* gob = &g_o[(size_t)hk * NTILE * TILE * DHEAD + dbase];
        #pragma unroll
        for (int l = 0; l < 8; l++) {
            int e = tid + l * 128;
            int row = e >> 3, c4 = e & 7;
            float4 v = *(const float4*)&gob[(size_t)rowoff[l] * DHEAD + c4 * 4];
            *(float4*)&As[row * 36 + c4 * 4] = v;   // g_o already tf32
        }
        #pragma unroll
        for (int l = 0; l < 8; l++) {
            int e = tid + l * 128;
            int k = e >> 5, c4 = e & 31;
            float4 v = *(const float4*)&Wo[(kk + k) * HID + n0 + c4 * 4];
            v.x = tff(v.x); v.y = tff(v.y); v.z = tff(v.z); v.w = tff(v.w);
            *(float4*)&Bs[k * 136 + c4 * 4] = v;
        }
        __syncthreads();

        #pragma unroll
        for (int ks = 0; ks < 4; ks++) {
            unsigned a[4][4], b[8][2];
            #pragma unroll
            for (int mf = 0; mf < 4; mf++) {
                const float* p = &As[(wm * 64 + mf * 16 + g) * 36 + ks * 8 + c];
                a[mf][0] = __float_as_uint(p[0]);
                a[mf][1] = __float_as_uint(p[8 * 36]);
                a[mf][2] = __float_as_uint(p[4]);
                a[mf][3] = __float_as_uint(p[8 * 36 + 4]);
            }
            #pragma unroll
            for (int nf = 0; nf < 8; nf++) {
                int col = wn * 64 + nf * 8 + g;
                b[nf][0] = __float_as_uint(Bs[(ks * 8 + c) * 136 + col]);
                b[nf][1] = __float_as_uint(Bs[(ks * 8 + c + 4) * 136 + col]);
            }
            #pragma unroll
            for (int mf = 0; mf < 4; mf++)
                #pragma unroll
                for (int nf = 0; nf < 8; nf++)
                    mma_tf32(acc[mf][nf][0], acc[mf][nf][1], acc[mf][nf][2], acc[mf][nf][3],
                             a[mf][0], a[mf][1], a[mf][2], a[mf][3], b[nf][0], b[nf][1]);
        }
        __syncthreads();
    }

    #pragma unroll
    for (int mf = 0; mf < 4; mf++) {
        int r0 = m0 + wm * 64 + mf * 16 + g;
        int r1 = r0 + 8;
        #pragma unroll
        for (int nf = 0; nf < 8; nf++) {
            int col = n0 + wn * 64 + nf * 8 + 2 * c;
            *(float2*)&out[r0 * HID + col] = make_float2(acc[mf][nf][0], acc[mf][nf][1]);
            *(float2*)&out[r1 * HID + col] = make_float2(acc[mf][nf][2], acc[mf][nf][3]);
        }
    }
}

extern "C" void kernel_launch(void* const* d_in, const int* in_sizes, int n_in,
                              void* d_out, int out_size)
{
    const float* X  = (const float*)d_in[0];
    const float* Wq = (const float*)d_in[1];
    const float* Wk = (const float*)d_in[2];
    const float* Wv = (const float*)d_in[3];
    const float* Wo = (const float*)d_in[4];
    float* out = (float*)d_out;

    dim3 gqkv(8, 64, 3);
    qkv_gemm<<<gqkv, 128>>>(X, Wq, Wk, Wv);

    attn_kernel<<<NHEADS * NTILE, 256>>>();

    dim3 gop(8, 64);
    oproj_gemm<<<gop, 128>>>(Wo, out);
}

// round 5
// speedup vs baseline: 1.3574x; 1.3574x over previous
#include <cuda_runtime.h>

// Problem constants
#define NHEADS 16
#define DHEAD  64
#define NTILE  64
#define TILE   128
#define SEQ    8192
#define HID    1024

// Scratch: tiled Q/K/V/O, layout [NH][NTILE][TILE][D], values tf32-rounded
__device__ float g_q[NHEADS * NTILE * TILE * DHEAD];
__device__ float g_k[NHEADS * NTILE * TILE * DHEAD];
__device__ float g_v[NHEADS * NTILE * TILE * DHEAD];
__device__ float g_o[NHEADS * NTILE * TILE * DHEAD];

__device__ __forceinline__ void seq_to_tile(int s, int& n, int& p) {
    int t = s >> 10;
    int h = (s >> 5) & 31;
    int w = s & 31;
    n = (((t >> 1) * 4 + (h >> 3)) * 4 + (w >> 3));
    p = (((t & 1) * 8 + (h & 7)) * 8 + (w & 7));
}

__device__ __forceinline__ unsigned f2tf32(float x) {
    unsigned u;
    asm("cvt.rna.tf32.f32 %0, %1;" : "=r"(u) : "f"(x));
    return u;
}
__device__ __forceinline__ float tff(float x) { return __uint_as_float(f2tf32(x)); }

__device__ __forceinline__ float ex2(float x) {
    float y;
    asm("ex2.approx.f32 %0, %1;" : "=f"(y) : "f"(x));
    return y;
}

__device__ __forceinline__ void mma_tf32(float& c0, float& c1, float& c2, float& c3,
                                         unsigned a0, unsigned a1, unsigned a2, unsigned a3,
                                         unsigned b0, unsigned b1) {
    asm volatile(
        "mma.sync.aligned.m16n8k8.row.col.f32.tf32.tf32.f32 "
        "{%0,%1,%2,%3},{%4,%5,%6,%7},{%8,%9},{%0,%1,%2,%3};"
        : "+f"(c0), "+f"(c1), "+f"(c2), "+f"(c3)
        : "r"(a0), "r"(a1), "r"(a2), "r"(a3), "r"(b0), "r"(b1));
}

// ---------------------------------------------------------------------------
// QKV projection: 128x128 block tile, 256 threads (8 warps, 2x4),
// warp tile 64x32, K-chunk 32, 2 CTAs/SM. grid (8, 64, 3).
// ---------------------------------------------------------------------------
__global__ __launch_bounds__(256, 2) void qkv_gemm(
    const float* __restrict__ X,
    const float* __restrict__ Wq,
    const float* __restrict__ Wk,
    const float* __restrict__ Wv)
{
    const float* W = (blockIdx.z == 0) ? Wq : (blockIdx.z == 1) ? Wk : Wv;
    float* Out = (blockIdx.z == 0) ? g_q : (blockIdx.z == 1) ? g_k : g_v;

    const int m0 = blockIdx.y * 128;
    const int n0 = blockIdx.x * 128;

    __shared__ float As[128 * 36];   // [m][k] stride 36
    __shared__ float Bs[32 * 136];   // [k][n] stride 136

    const int tid = threadIdx.x;
    const int warp = tid >> 5, lane = tid & 31;
    const int g = lane >> 2, c = lane & 3;
    const int wm = warp >> 2, wn = warp & 3;     // 2 x 4 warp grid

    float acc[4][4][4] = {};

    for (int kk = 0; kk < HID; kk += 32) {
        #pragma unroll
        for (int l = 0; l < 4; l++) {
            int e = tid + l * 256;
            int row = e >> 3, c4 = e & 7;
            float4 v = *(const float4*)&X[(m0 + row) * HID + kk + c4 * 4];
            v.x = tff(v.x); v.y = tff(v.y); v.z = tff(v.z); v.w = tff(v.w);
            *(float4*)&As[row * 36 + c4 * 4] = v;
        }
        #pragma unroll
        for (int l = 0; l < 4; l++) {
            int e = tid + l * 256;
            int k = e >> 5, c4 = e & 31;
            float4 v = *(const float4*)&W[(kk + k) * HID + n0 + c4 * 4];
            v.x = tff(v.x); v.y = tff(v.y); v.z = tff(v.z); v.w = tff(v.w);
            *(float4*)&Bs[k * 136 + c4 * 4] = v;
        }
        __syncthreads();

        #pragma unroll
        for (int ks = 0; ks < 4; ks++) {
            unsigned a[4][4], b[4][2];
            #pragma unroll
            for (int mf = 0; mf < 4; mf++) {
                const float* p = &As[(wm * 64 + mf * 16 + g) * 36 + ks * 8 + c];
                a[mf][0] = __float_as_uint(p[0]);
                a[mf][1] = __float_as_uint(p[8 * 36]);
                a[mf][2] = __float_as_uint(p[4]);
                a[mf][3] = __float_as_uint(p[8 * 36 + 4]);
            }
            #pragma unroll
            for (int nf = 0; nf < 4; nf++) {
                int col = wn * 32 + nf * 8 + g;
                b[nf][0] = __float_as_uint(Bs[(ks * 8 + c) * 136 + col]);
                b[nf][1] = __float_as_uint(Bs[(ks * 8 + c + 4) * 136 + col]);
            }
            #pragma unroll
            for (int mf = 0; mf < 4; mf++)
                #pragma unroll
                for (int nf = 0; nf < 4; nf++)
                    mma_tf32(acc[mf][nf][0], acc[mf][nf][1], acc[mf][nf][2], acc[mf][nf][3],
                             a[mf][0], a[mf][1], a[mf][2], a[mf][3], b[nf][0], b[nf][1]);
        }
        __syncthreads();
    }

    #pragma unroll
    for (int mf = 0; mf < 4; mf++) {
        int r0 = m0 + wm * 64 + mf * 16 + g;
        int r1 = r0 + 8;
        int n_, p_, n2, p2;
        seq_to_tile(r0, n_, p_);
        seq_to_tile(r1, n2, p2);
        #pragma unroll
        for (int nf = 0; nf < 4; nf++) {
            int colg = n0 + wn * 32 + nf * 8 + 2 * c;
            int head = colg >> 6, d = colg & 63;
            float2 v0 = make_float2(tff(acc[mf][nf][0]), tff(acc[mf][nf][1]));
            float2 v1 = make_float2(tff(acc[mf][nf][2]), tff(acc[mf][nf][3]));
            *(float2*)&Out[((head * NTILE + n_) * TILE + p_) * DHEAD + d] = v0;
            *(float2*)&Out[((head * NTILE + n2) * TILE + p2) * DHEAD + d] = v1;
        }
    }
}

// ---------------------------------------------------------------------------
// Flash attention. 1 block per (head, q-tile): 1024 blocks, 128 threads
// (4 warps); each warp owns 32 q rows as TWO 16-row A fragments so every
// K/V B-fragment LDS feeds two mmas (1.0 LDS/mma). 64-key chunks.
// P never touches smem (permuted-A trick: (c0,c2,c1,c3) + V rows 2c,2c+1).
// ---------------------------------------------------------------------------
__global__ __launch_bounds__(128) void attn_kernel()
{
    const int bid = blockIdx.x;
    const int head = bid >> 6;
    const int n = bid & 63;
    const int tid = threadIdx.x;
    const int warp = tid >> 5, lane = tid & 31;
    const int g = lane >> 2, c = lane & 3;

    __shared__ float Ks[64 * 68];   // [key][d] stride 68
    __shared__ float Vs[64 * 68];

    const float SC = 0.125f * 1.4426950408889634f;   // 1/sqrt(D) * log2e
    unsigned Qf[2][8][4];
    {
        const float* qb = &g_q[(size_t)((head * NTILE + n) * TILE) * DHEAD];
        #pragma unroll
        for (int rb = 0; rb < 2; rb++) {
            int r = warp * 32 + rb * 16 + g;
            #pragma unroll
            for (int kf = 0; kf < 8; kf++) {
                int col = kf * 8 + c;
                Qf[rb][kf][0] = f2tf32(qb[r * 64 + col] * SC);
                Qf[rb][kf][1] = f2tf32(qb[(r + 8) * 64 + col] * SC);
                Qf[rb][kf][2] = f2tf32(qb[r * 64 + col + 4] * SC);
                Qf[rb][kf][3] = f2tf32(qb[(r + 8) * 64 + col + 4] * SC);
            }
        }
    }

    float O[2][8][4] = {};
    float m_[2][2], l_[2][2];
    #pragma unroll
    for (int rb = 0; rb < 2; rb++) {
        m_[rb][0] = -1e30f; m_[rb][1] = -1e30f;
        l_[rb][0] = 0.f;    l_[rb][1] = 0.f;
    }

    const int ntt = n >> 4, nth = (n >> 2) & 3, ntw = n & 3;
    const int ct = min(max(ntt, 1), 2);
    const int ch = min(max(nth, 1), 3);
    const int cw = min(max(ntw, 1), 3);

    for (int kk = 0; kk < 12; kk++) {
        const int it = kk >> 2, ih = (kk >> 1) & 1, iw = kk & 1;
        const int kvn = ((ct - 1 + it) * 4 + (ch - 1 + ih)) * 4 + (cw - 1 + iw);
        const float* kb = &g_k[(size_t)((head * NTILE + kvn) * TILE) * DHEAD];
        const float* vb = &g_v[(size_t)((head * NTILE + kvn) * TILE) * DHEAD];

        for (int cc = 0; cc < 2; cc++) {
            __syncthreads();
            #pragma unroll
            for (int l2 = 0; l2 < 8; l2++) {
                int e = tid + l2 * 128;
                int key = e >> 4, c4 = e & 15;
                *(float4*)&Ks[key * 68 + c4 * 4] =
                    *(const float4*)&kb[(cc * 64 + key) * 64 + c4 * 4];
                *(float4*)&Vs[key * 68 + c4 * 4] =
                    *(const float4*)&vb[(cc * 64 + key) * 64 + c4 * 4];
            }
            __syncthreads();

            // S = Q*K^T: 32 rows x 64 keys per warp; B frag shared by both rbs
            float S[2][8][4] = {};
            #pragma unroll
            for (int ks = 0; ks < 8; ks++) {
                #pragma unroll
                for (int nf = 0; nf < 8; nf++) {
                    int key = nf * 8 + g;
                    unsigned b0 = __float_as_uint(Ks[key * 68 + ks * 8 + c]);
                    unsigned b1 = __float_as_uint(Ks[key * 68 + ks * 8 + c + 4]);
                    mma_tf32(S[0][nf][0], S[0][nf][1], S[0][nf][2], S[0][nf][3],
                             Qf[0][ks][0], Qf[0][ks][1], Qf[0][ks][2], Qf[0][ks][3], b0, b1);
                    mma_tf32(S[1][nf][0], S[1][nf][1], S[1][nf][2], S[1][nf][3],
                             Qf[1][ks][0], Qf[1][ks][1], Qf[1][ks][2], Qf[1][ks][3], b0, b1);
                }
            }

            // online softmax (base-2) per row-block
            #pragma unroll
            for (int rb = 0; rb < 2; rb++) {
                float rmax0 = -1e30f, rmax1 = -1e30f;
                #pragma unroll
                for (int nf = 0; nf < 8; nf++) {
                    rmax0 = fmaxf(rmax0, fmaxf(S[rb][nf][0], S[rb][nf][1]));
                    rmax1 = fmaxf(rmax1, fmaxf(S[rb][nf][2], S[rb][nf][3]));
                }
                rmax0 = fmaxf(rmax0, __shfl_xor_sync(0xffffffffu, rmax0, 1));
                rmax0 = fmaxf(rmax0, __shfl_xor_sync(0xffffffffu, rmax0, 2));
                rmax1 = fmaxf(rmax1, __shfl_xor_sync(0xffffffffu, rmax1, 1));
                rmax1 = fmaxf(rmax1, __shfl_xor_sync(0xffffffffu, rmax1, 2));

                float mn0 = fmaxf(m_[rb][0], rmax0), mn1 = fmaxf(m_[rb][1], rmax1);
                float sf0 = ex2(m_[rb][0] - mn0), sf1 = ex2(m_[rb][1] - mn1);

                float rs0 = 0.f, rs1 = 0.f;
                #pragma unroll
                for (int nf = 0; nf < 8; nf++) {
                    S[rb][nf][0] = ex2(S[rb][nf][0] - mn0);
                    S[rb][nf][1] = ex2(S[rb][nf][1] - mn0);
                    S[rb][nf][2] = ex2(S[rb][nf][2] - mn1);
                    S[rb][nf][3] = ex2(S[rb][nf][3] - mn1);
                    rs0 += S[rb][nf][0] + S[rb][nf][1];
                    rs1 += S[rb][nf][2] + S[rb][nf][3];
                }
                rs0 += __shfl_xor_sync(0xffffffffu, rs0, 1);
                rs0 += __shfl_xor_sync(0xffffffffu, rs0, 2);
                rs1 += __shfl_xor_sync(0xffffffffu, rs1, 1);
                rs1 += __shfl_xor_sync(0xffffffffu, rs1, 2);

                l_[rb][0] = l_[rb][0] * sf0 + rs0;
                l_[rb][1] = l_[rb][1] * sf1 + rs1;
                m_[rb][0] = mn0; m_[rb][1] = mn1;

                #pragma unroll
                for (int nf = 0; nf < 8; nf++) {
                    O[rb][nf][0] *= sf0; O[rb][nf][1] *= sf0;
                    O[rb][nf][2] *= sf1; O[rb][nf][3] *= sf1;
                }
            }

            // O += P*V; V B-frag shared by both row-blocks
            #pragma unroll
            for (int ko = 0; ko < 8; ko++) {
                unsigned pa[2][4];
                #pragma unroll
                for (int rb = 0; rb < 2; rb++) {
                    pa[rb][0] = f2tf32(S[rb][ko][0]);
                    pa[rb][1] = f2tf32(S[rb][ko][2]);
                    pa[rb][2] = f2tf32(S[rb][ko][1]);
                    pa[rb][3] = f2tf32(S[rb][ko][3]);
                }
                #pragma unroll
                for (int nf = 0; nf < 8; nf++) {
                    unsigned vb0 = __float_as_uint(Vs[(ko * 8 + 2 * c) * 68 + nf * 8 + g]);
                    unsigned vb1 = __float_as_uint(Vs[(ko * 8 + 2 * c + 1) * 68 + nf * 8 + g]);
                    mma_tf32(O[0][nf][0], O[0][nf][1], O[0][nf][2], O[0][nf][3],
                             pa[0][0], pa[0][1], pa[0][2], pa[0][3], vb0, vb1);
                    mma_tf32(O[1][nf][0], O[1][nf][1], O[1][nf][2], O[1][nf][3],
                             pa[1][0], pa[1][1], pa[1][2], pa[1][3], vb0, vb1);
                }
            }
        }
    }

    float* ob = &g_o[(size_t)((head * NTILE + n) * TILE) * DHEAD];
    #pragma unroll
    for (int rb = 0; rb < 2; rb++) {
        const float inv0 = 1.f / l_[rb][0], inv1 = 1.f / l_[rb][1];
        int r = warp * 32 + rb * 16 + g;
        #pragma unroll
        for (int nf = 0; nf < 8; nf++) {
            int col = nf * 8 + 2 * c;
            *(float2*)&ob[r * 64 + col] =
                make_float2(tff(O[rb][nf][0] * inv0), tff(O[rb][nf][1] * inv0));
            *(float2*)&ob[(r + 8) * 64 + col] =
                make_float2(tff(O[rb][nf][2] * inv1), tff(O[rb][nf][3] * inv1));
        }
    }
}

// ---------------------------------------------------------------------------
// Output projection: out = O_seq @ Wo, _from_tiles remap fused into A fill.
// Same shape as qkv_gemm: 256 threads, 2 CTAs/SM. grid (8, 64).
// ---------------------------------------------------------------------------
__global__ __launch_bounds__(256, 2) void oproj_gemm(
    const float* __restrict__ Wo, float* __restrict__ out)
{
    const int m0 = blockIdx.y * 128;
    const int n0 = blockIdx.x * 128;

    __shared__ float As[128 * 36];
    __shared__ float Bs[32 * 136];

    const int tid = threadIdx.x;
    const int warp = tid >> 5, lane = tid & 31;
    const int g = lane >> 2, c = lane & 3;
    const int wm = warp >> 2, wn = warp & 3;

    // hoist tile remap for this thread's 4 A rows
    int rowoff[4];
    #pragma unroll
    for (int l = 0; l < 4; l++) {
        int e = tid + l * 256;
        int row = e >> 3;
        int nn, pp;
        seq_to_tile(m0 + row, nn, pp);
        rowoff[l] = nn * TILE + pp;
    }

    float acc[4][4][4] = {};

    for (int kk = 0; kk < HID; kk += 32) {
        const int hk = kk >> 6;
        const int dbase = kk & 63;
        const float* gob = &g_o[(size_t)hk * NTILE * TILE * DHEAD + dbase];
        #pragma unroll
        for (int l = 0; l < 4; l++) {
            int e = tid + l * 256;
            int row = e >> 3, c4 = e & 7;
            float4 v = *(const float4*)&gob[(size_t)rowoff[l] * DHEAD + c4 * 4];
            *(float4*)&As[row * 36 + c4 * 4] = v;   // g_o already tf32
        }
        #pragma unroll
        for (int l = 0; l < 4; l++) {
            int e = tid + l * 256;
            int k = e >> 5, c4 = e & 31;
            float4 v = *(const float4*)&Wo[(kk + k) * HID + n0 + c4 * 4];
            v.x = tff(v.x); v.y = tff(v.y); v.z = tff(v.z); v.w = tff(v.w);
            *(float4*)&Bs[k * 136 + c4 * 4] = v;
        }
        __syncthreads();

        #pragma unroll
        for (int ks = 0; ks < 4; ks++) {
            unsigned a[4][4], b[4][2];
            #pragma unroll
            for (int mf = 0; mf < 4; mf++) {
                const float* p = &As[(wm * 64 + mf * 16 + g) * 36 + ks * 8 + c];
                a[mf][0] = __float_as_uint(p[0]);
                a[mf][1] = __float_as_uint(p[8 * 36]);
                a[mf][2] = __float_as_uint(p[4]);
                a[mf][3] = __float_as_uint(p[8 * 36 + 4]);
            }
            #pragma unroll
            for (int nf = 0; nf < 4; nf++) {
                int col = wn * 32 + nf * 8 + g;
                b[nf][0] = __float_as_uint(Bs[(ks * 8 + c) * 136 + col]);
                b[nf][1] = __float_as_uint(Bs[(ks * 8 + c + 4) * 136 + col]);
            }
            #pragma unroll
            for (int mf = 0; mf < 4; mf++)
                #pragma unroll
                for (int nf = 0; nf < 4; nf++)
                    mma_tf32(acc[mf][nf][0], acc[mf][nf][1], acc[mf][nf][2], acc[mf][nf][3],
                             a[mf][0], a[mf][1], a[mf][2], a[mf][3], b[nf][0], b[nf][1]);
        }
        __syncthreads();
    }

    #pragma unroll
    for (int mf = 0; mf < 4; mf++) {
        int r0 = m0 + wm * 64 + mf * 16 + g;
        int r1 = r0 + 8;
        #pragma unroll
        for (int nf = 0; nf < 4; nf++) {
            int col = n0 + wn * 32 + nf * 8 + 2 * c;
            *(float2*)&out[r0 * HID + col] = make_float2(acc[mf][nf][0], acc[mf][nf][1]);
            *(float2*)&out[r1 * HID + col] = make_float2(acc[mf][nf][2], acc[mf][nf][3]);
        }
    }
}

extern "C" void kernel_launch(void* const* d_in, const int* in_sizes, int n_in,
                              void* d_out, int out_size)
{
    const float* X  = (const float*)d_in[0];
    const float* Wq = (const float*)d_in[1];
    const float* Wk = (const float*)d_in[2];
    const float* Wv = (const float*)d_in[3];
    const float* Wo = (const float*)d_in[4];
    float* out = (float*)d_out;

    dim3 gqkv(8, 64, 3);
    qkv_gemm<<<gqkv, 256>>>(X, Wq, Wk, Wv);

    attn_kernel<<<NHEADS * NTILE, 128>>>();

    dim3 gop(8, 64);
    oproj_gemm<<<gop, 256>>>(Wo, out);
}